// round 10
// baseline (speedup 1.0000x reference)
#include <cuda_runtime.h>
#include <cuda_bf16.h>
#include <cstdint>

// Problem constants (fixed by the dataset problem)
#define NN   16384          // nodes
#define DD   128            // feature dim (in == out)
#define EE   524288         // edges
#define ROWCAP 192          // per-row slot cap (max expected degree ~57)
#define GEMM_ROWS 128
#define NBLK_GEMM (NN / GEMM_ROWS)                 // 128
#define FILL_U 8
#define FILL_THREADS 256
#define FILL_EBLK (FILL_THREADS * FILL_U)          // 2048 edges/block
#define NBLK_FILL (EE / FILL_EBLK)                 // 256

// ---------------- device scratch (no allocations allowed) ----------------
__device__ float g_h[NN * DD];                 // 8 MB   h = x @ W
__device__ float g_s1[NN];
__device__ float g_s2[NN];
__device__ float g_Sh[DD];                     // total column sums
__device__ float g_ShPart[NBLK_GEMM][DD];      // per-gemm-block partial column sums
__device__ int   g_done;                       // gemm-block completion counter (self-reset)
__device__ int   g_cnt[NN];                    // zero at start of every call (self-cleaning)
__device__ int   g_cols[NN * ROWCAP];          // slotted adjacency, 12.6 MB

__device__ __forceinline__ void mma_bf16(float* d, uint32_t a0, uint32_t a1,
                                         uint32_t a2, uint32_t a3,
                                         uint32_t b0, uint32_t b1) {
    asm volatile(
        "mma.sync.aligned.m16n8k16.row.col.f32.bf16.bf16.f32 "
        "{%0,%1,%2,%3}, {%4,%5,%6,%7}, {%8,%9}, {%0,%1,%2,%3};"
        : "+f"(d[0]), "+f"(d[1]), "+f"(d[2]), "+f"(d[3])
        : "r"(a0), "r"(a1), "r"(a2), "r"(a3), "r"(b0), "r"(b1));
}

// ---------------- fused kernel: blocks [0,128) tensor-core gemm, [128,384) fill
//   gemm: 128 rows x 128 cols per block via 3-term bf16-split HMMA (~1.5e-5 rel).
//   Last gemm block reduces ShPart -> Sh (fence+counter, self-cleaning).
//   fill: slotted CSR scatter; independent of gemm, overlaps with it.
__global__ void __launch_bounds__(256, 2)
k_main(const float* __restrict__ x, const float* __restrict__ W,
       const float* __restrict__ a, const void* __restrict__ ei) {
    __shared__ __nv_bfloat16 xhi[128][36];   // x chunk hi, k-pad 36 (9 KB)
    __shared__ __nv_bfloat16 xlo[128][36];   // x chunk lo              (9 KB)
    __shared__ __nv_bfloat16 whi[128][36];   // W chunk hi, [n][k]      (9 KB)
    __shared__ __nv_bfloat16 wlo[128][36];   // W chunk lo              (9 KB)
    __shared__ float shc[128];               // block column sums
    __shared__ int   s_flag;                 // is64 (fill) / last-block (gemm)

    const int tid = threadIdx.x;

    if (blockIdx.x >= NBLK_GEMM) {
        // ---------------- fill branch ----------------
        if (tid == 0) {
            const int* p = (const int*)ei;
            int z = 0;
            #pragma unroll
            for (int i = 0; i < 16; i++) z += (p[2 * i + 1] == 0);
            s_flag = (z == 16);      // int64-LE, values<2^31 -> odd words zero
        }
        __syncthreads();
        const bool is64 = (s_flag != 0);

        const int base = (blockIdx.x - NBLK_GEMM) * FILL_EBLK + tid;
        int rr[FILL_U], cc[FILL_U];
        if (is64) {
            const long long* p = (const long long*)ei;
            #pragma unroll
            for (int u = 0; u < FILL_U; u++) {
                int e = base + u * FILL_THREADS;
                rr[u] = (int)p[e];
                cc[u] = (int)p[(long long)EE + e];
            }
        } else {
            const int* p = (const int*)ei;
            #pragma unroll
            for (int u = 0; u < FILL_U; u++) {
                int e = base + u * FILL_THREADS;
                rr[u] = p[e];
                cc[u] = p[EE + e];
            }
        }
        #pragma unroll
        for (int u = 0; u < FILL_U; u++) {
            int slot = atomicAdd(&g_cnt[rr[u]], 1);
            if (slot < ROWCAP) g_cols[rr[u] * ROWCAP + slot] = cc[u];
        }
        return;
    }

    // ---------------- tensor-core gemm branch ----------------
    const int warp = tid >> 5;               // 0..7 -> rows warp*16..+15
    const int lane = tid & 31;
    const int grp  = lane >> 2;              // 0..7
    const int kq   = (lane & 3) * 2;         // 0,2,4,6
    const int bm   = blockIdx.x * GEMM_ROWS;

    float acc[16][4];                        // 16 n-tiles of m16n8, fp32
    #pragma unroll
    for (int t = 0; t < 16; t++) {
        acc[t][0] = 0.f; acc[t][1] = 0.f; acc[t][2] = 0.f; acc[t][3] = 0.f;
    }

    for (int k0 = 0; k0 < DD; k0 += 32) {
        // load x chunk 128x32 fp32, split to bf16 hi/lo (1024 float4, 4/thread)
        #pragma unroll
        for (int i = 0; i < 4; i++) {
            int idx = tid + i * 256;
            int r = idx >> 3, c4 = (idx & 7) * 4;
            float4 v = ((const float4*)x)[(bm + r) * 32 + (k0 >> 2) + (idx & 7)];
            float vv[4] = {v.x, v.y, v.z, v.w};
            #pragma unroll
            for (int j = 0; j < 4; j++) {
                __nv_bfloat16 hi = __float2bfloat16_rn(vv[j]);
                xhi[r][c4 + j] = hi;
                xlo[r][c4 + j] = __float2bfloat16_rn(vv[j] - __bfloat162float(hi));
            }
        }
        // load W chunk 32x128 fp32, transpose to [n][k], split hi/lo
        #pragma unroll
        for (int i = 0; i < 4; i++) {
            int idx = tid + i * 256;
            int kk = idx >> 5, n4 = (idx & 31) * 4;
            float4 v = ((const float4*)W)[(k0 + kk) * 32 + (idx & 31)];
            float vv[4] = {v.x, v.y, v.z, v.w};
            #pragma unroll
            for (int j = 0; j < 4; j++) {
                __nv_bfloat16 hi = __float2bfloat16_rn(vv[j]);
                whi[n4 + j][kk] = hi;
                wlo[n4 + j][kk] = __float2bfloat16_rn(vv[j] - __bfloat162float(hi));
            }
        }
        __syncthreads();

        #pragma unroll
        for (int ks = 0; ks < 32; ks += 16) {
            const int r0 = warp * 16 + grp;
            uint32_t ah0 = *(const uint32_t*)&xhi[r0][ks + kq];
            uint32_t ah1 = *(const uint32_t*)&xhi[r0 + 8][ks + kq];
            uint32_t ah2 = *(const uint32_t*)&xhi[r0][ks + kq + 8];
            uint32_t ah3 = *(const uint32_t*)&xhi[r0 + 8][ks + kq + 8];
            uint32_t al0 = *(const uint32_t*)&xlo[r0][ks + kq];
            uint32_t al1 = *(const uint32_t*)&xlo[r0 + 8][ks + kq];
            uint32_t al2 = *(const uint32_t*)&xlo[r0][ks + kq + 8];
            uint32_t al3 = *(const uint32_t*)&xlo[r0 + 8][ks + kq + 8];
            #pragma unroll
            for (int t = 0; t < 16; t++) {
                const int bn = t * 8 + grp;
                uint32_t bh0 = *(const uint32_t*)&whi[bn][ks + kq];
                uint32_t bh1 = *(const uint32_t*)&whi[bn][ks + kq + 8];
                uint32_t bl0 = *(const uint32_t*)&wlo[bn][ks + kq];
                uint32_t bl1 = *(const uint32_t*)&wlo[bn][ks + kq + 8];
                mma_bf16(acc[t], ah0, ah1, ah2, ah3, bh0, bh1);   // hi*hi
                mma_bf16(acc[t], ah0, ah1, ah2, ah3, bl0, bl1);   // hi*lo
                mma_bf16(acc[t], al0, al1, al2, al3, bh0, bh1);   // lo*hi
            }
        }
        __syncthreads();
    }

    // ---- epilogue from D fragments ----
    // thread holds rows r0 = bm+warp*16+grp, r1 = r0+8; cols t*8+kq, +1 per tile
    const int r0 = bm + warp * 16 + grp;
    const int r1 = r0 + 8;

    float p1r0 = 0.f, p1r1 = 0.f, p2r0 = 0.f, p2r1 = 0.f;
    #pragma unroll
    for (int t = 0; t < 16; t++) {
        const int c0 = t * 8 + kq;
        // h store (float2 = the two adjacent cols this thread owns)
        *(float2*)&g_h[r0 * DD + c0] = make_float2(acc[t][0], acc[t][1]);
        *(float2*)&g_h[r1 * DD + c0] = make_float2(acc[t][2], acc[t][3]);
        // s1/s2 partial dots
        float a10 = __ldg(&a[c0]), a11 = __ldg(&a[c0 + 1]);
        float a20 = __ldg(&a[DD + c0]), a21 = __ldg(&a[DD + c0 + 1]);
        p1r0 += acc[t][0] * a10 + acc[t][1] * a11;
        p1r1 += acc[t][2] * a10 + acc[t][3] * a11;
        p2r0 += acc[t][0] * a20 + acc[t][1] * a21;
        p2r1 += acc[t][2] * a20 + acc[t][3] * a21;
    }
    // reduce across the 4 lanes sharing each row (lane%4 group)
    #pragma unroll
    for (int o = 1; o <= 2; o <<= 1) {
        p1r0 += __shfl_xor_sync(0xffffffffu, p1r0, o);
        p1r1 += __shfl_xor_sync(0xffffffffu, p1r1, o);
        p2r0 += __shfl_xor_sync(0xffffffffu, p2r0, o);
        p2r1 += __shfl_xor_sync(0xffffffffu, p2r1, o);
    }
    if ((lane & 3) == 0) {
        g_s1[r0] = p1r0; g_s1[r1] = p1r1;
        g_s2[r0] = p2r0; g_s2[r1] = p2r1;
    }

    // column sums over this block's 128 rows
    if (tid < 128) shc[tid] = 0.0f;
    __syncthreads();
    #pragma unroll
    for (int t = 0; t < 16; t++) {
        const int c0 = t * 8 + kq;
        atomicAdd(&shc[c0],     acc[t][0] + acc[t][2]);
        atomicAdd(&shc[c0 + 1], acc[t][1] + acc[t][3]);
    }
    __syncthreads();
    if (tid < 128) g_ShPart[blockIdx.x][tid] = shc[tid];

    // last gemm block reduces ShPart -> Sh (fence+counter, deterministic)
    __threadfence();
    if (tid == 0)
        s_flag = (atomicAdd(&g_done, 1) == NBLK_GEMM - 1);
    __syncthreads();
    if (s_flag) {
        __threadfence();                      // acquire: see all ShPart writes
        if (tid < 128) {
            float s = 0.0f;
            #pragma unroll 8
            for (int b = 0; b < NBLK_GEMM; b++) s += g_ShPart[b][tid];
            g_Sh[tid] = s;
        }
        if (tid == 0) g_done = 0;             // self-clean for next replay
    }
}

// ---------------- out: warp per row; O(1) bitmap dedup in shared; int32 gather
//   indexing; 4-way unrolled L2 gather. Re-zeroes g_cnt[row] for next replay.
//   (Exact R9-measured version.)
__global__ void k_out(float* __restrict__ out) {
    __shared__ int      sc[8][ROWCAP];          // 6 KB
    __shared__ float    sw[8][ROWCAP];          // 6 KB
    __shared__ unsigned bmp[8][NN / 32];        // 16 KB: per-warp 16384-bit bitmap

    const int warp = threadIdx.x >> 5;
    const int lane = threadIdx.x & 31;
    const int row = blockIdx.x * 8 + warp;

    {
        uint4* bv = (uint4*)bmp[warp];
        uint4 z = make_uint4(0u, 0u, 0u, 0u);
        #pragma unroll
        for (int i = 0; i < 4; i++) bv[lane + i * 32] = z;
    }

    int cnt = g_cnt[row];
    if (cnt > ROWCAP) cnt = ROWCAP;
    const int base = row * ROWCAP;
    const float s1i = g_s1[row];

    for (int j = lane; j < cnt; j += 32) sc[warp][j] = g_cols[base + j];
    __syncwarp();

    if (lane == 0) g_cnt[row] = 0;

    for (int j = lane; j < cnt; j += 32) {
        int c = sc[warp][j];
        unsigned bit = 1u << (c & 31);
        unsigned old = atomicOr(&bmp[warp][c >> 5], bit);
        float w = 0.0f;
        if (!(old & bit)) {
            float e = s1i + __ldg(&g_s2[c]);
            e = (e > 0.0f) ? e : 0.2f * e;       // LeakyReLU(0.2)
            w = __expf(e) - 1.0f;                // exp(e) - exp(0)
        }
        sw[warp][j] = w;
    }
    __syncwarp();

    const float4* hb = (const float4*)g_h;
    float4 acc = make_float4(0.f, 0.f, 0.f, 0.f);
    float wsum = 0.0f;

    int t = 0;
    for (; t + 4 <= cnt; t += 4) {
        const int   c0 = sc[warp][t],     c1 = sc[warp][t + 1];
        const int   c2 = sc[warp][t + 2], c3 = sc[warp][t + 3];
        const float w0 = sw[warp][t],     w1 = sw[warp][t + 1];
        const float w2 = sw[warp][t + 2], w3 = sw[warp][t + 3];
        const float4 hv0 = hb[c0 * 32 + lane];
        const float4 hv1 = hb[c1 * 32 + lane];
        const float4 hv2 = hb[c2 * 32 + lane];
        const float4 hv3 = hb[c3 * 32 + lane];
        acc.x += w0 * hv0.x; acc.y += w0 * hv0.y; acc.z += w0 * hv0.z; acc.w += w0 * hv0.w; wsum += w0;
        acc.x += w1 * hv1.x; acc.y += w1 * hv1.y; acc.z += w1 * hv1.z; acc.w += w1 * hv1.w; wsum += w1;
        acc.x += w2 * hv2.x; acc.y += w2 * hv2.y; acc.z += w2 * hv2.z; acc.w += w2 * hv2.w; wsum += w2;
        acc.x += w3 * hv3.x; acc.y += w3 * hv3.y; acc.z += w3 * hv3.z; acc.w += w3 * hv3.w; wsum += w3;
    }
    for (; t < cnt; t++) {
        const int   c0 = sc[warp][t];
        const float w0 = sw[warp][t];
        const float4 hv0 = hb[c0 * 32 + lane];
        acc.x += w0 * hv0.x; acc.y += w0 * hv0.y; acc.z += w0 * hv0.z; acc.w += w0 * hv0.w;
        wsum += w0;
    }

    const float4 sh = ((const float4*)g_Sh)[lane];
    const float inv = 1.0f / ((float)NN + wsum);
    float4 o;
    o.x = (sh.x + acc.x) * inv;
    o.y = (sh.y + acc.y) * inv;
    o.z = (sh.z + acc.z) * inv;
    o.w = (sh.w + acc.w) * inv;
    ((float4*)out)[row * 32 + lane] = o;
}

// ---------------- launcher: 2 graph nodes ----------------
extern "C" void kernel_launch(void* const* d_in, const int* in_sizes, int n_in,
                              void* d_out, int out_size) {
    const float* x  = (const float*)d_in[0];   // [16384,128] f32
    const void*  ei = d_in[1];                 // [2,524288] int64 (or int32 — detected)
    const float* W  = (const float*)d_in[2];   // [128,128] f32
    const float* a  = (const float*)d_in[3];   // [256] f32
    float* out = (float*)d_out;                // [16384,128] f32

    k_main<<<NBLK_GEMM + NBLK_FILL, 256>>>(x, W, a, ei);
    k_out<<<NN / 8, 256>>>(out);
}

// round 11
// speedup vs baseline: 1.7194x; 1.7194x over previous
#include <cuda_runtime.h>
#include <cuda_bf16.h>
#include <cuda_fp16.h>
#include <cstdint>

// Problem constants (fixed by the dataset problem)
#define NN   16384          // nodes
#define DD   128            // feature dim (in == out)
#define EE   524288         // edges
#define ROWCAP 192          // per-row slot cap (max expected degree ~57)
#define NBLK_GEMM (NN / 64) // 256
#define FILL_U 4
#define FILL_THREADS 512
#define FILL_EBLK (FILL_THREADS * FILL_U)          // 2048 edges/block
#define NBLK_FILL (EE / FILL_EBLK)                 // 256

// ---------------- device scratch (no allocations allowed) ----------------
__device__ __half g_hh[NN * DD];               // 4 MB   h = x @ W, fp16 (gather-only use)
__device__ float g_s1[NN];
__device__ float g_s2[NN];
__device__ float g_Sh[DD];                     // total column sums (fp32, from accumulators)
__device__ float g_ShPart[NBLK_GEMM][DD];      // per-gemm-block partial column sums
__device__ int   g_done;                       // gemm-block completion counter (self-reset)
__device__ int   g_cnt[NN];                    // zero at start of every call (self-cleaning)
__device__ int   g_cols[NN * ROWCAP];          // slotted adjacency, 12.6 MB

// ---------------- fused kernel: blocks [0,256) gemm, blocks [256,512) edge fill
//   gemm: 64 rows x 128 cols per block, 512 threads, 4x4 per thread (R9-measured).
//   h stored fp16 (only the k_out gather reads it); s1/s2/Sh from fp32 accs.
//   Last gemm block reduces ShPart -> Sh (fence+counter, self-cleaning).
__global__ void k_main(const float* __restrict__ x, const float* __restrict__ W,
                       const float* __restrict__ a, const void* __restrict__ ei) {
    __shared__ float xs[64][36];    // [m][k], padded          (gemm branch)
    __shared__ float ws[32][128];   // [k][n]                  (gemm branch)
    __shared__ float shc[128];      // block column sums       (gemm branch)
    __shared__ float red[4][128];   // ShPart reduction        (last gemm block)
    __shared__ int   s_flag;        // is64 (fill) / last-block (gemm)

    if (blockIdx.x >= NBLK_GEMM) {
        // ---------------- fill branch ----------------
        if (threadIdx.x == 0) {
            const int* p = (const int*)ei;
            int z = 0;
            #pragma unroll
            for (int i = 0; i < 16; i++) z += (p[2 * i + 1] == 0);
            s_flag = (z == 16);      // int64-LE, values<2^31 -> odd words zero
        }
        __syncthreads();
        const bool is64 = (s_flag != 0);

        const int base = (blockIdx.x - NBLK_GEMM) * FILL_EBLK + threadIdx.x;
        int rr[FILL_U], cc[FILL_U];
        if (is64) {
            const long long* p = (const long long*)ei;
            #pragma unroll
            for (int u = 0; u < FILL_U; u++) {
                int e = base + u * FILL_THREADS;
                rr[u] = (int)p[e];
                cc[u] = (int)p[(long long)EE + e];
            }
        } else {
            const int* p = (const int*)ei;
            #pragma unroll
            for (int u = 0; u < FILL_U; u++) {
                int e = base + u * FILL_THREADS;
                rr[u] = p[e];
                cc[u] = p[EE + e];
            }
        }
        #pragma unroll
        for (int u = 0; u < FILL_U; u++) {
            int slot = atomicAdd(&g_cnt[rr[u]], 1);
            if (slot < ROWCAP) g_cols[rr[u] * ROWCAP + slot] = cc[u];
        }
        return;
    }

    // ---------------- gemm branch (identical math to the 56.3us kernel) ----------------
    const int tx = threadIdx.x & 31;        // 0..31 -> cols tx*4 .. tx*4+3
    const int ty = threadIdx.x >> 5;        // 0..15 -> rows ty*4 .. ty*4+3
    const int bm = blockIdx.x * 64;

    float4 acc[4];
    #pragma unroll
    for (int m = 0; m < 4; m++) acc[m] = make_float4(0.f, 0.f, 0.f, 0.f);

    for (int k0 = 0; k0 < DD; k0 += 32) {
        {   // x tile: 64 rows x 32 k = 512 float4, one per thread
            int i = threadIdx.x;
            int r = i >> 3, c4 = i & 7;
            float4 v = ((const float4*)x)[(long long)(bm + r) * (DD / 4) + (k0 >> 2) + c4];
            *(float4*)&xs[r][c4 * 4] = v;
        }
        #pragma unroll
        for (int i = 0; i < 2; i++) {   // W tile: 32 k x 128 n = 1024 float4
            int idx = threadIdx.x + i * 512;
            int kk = idx >> 5, n4 = idx & 31;
            float4 v = ((const float4*)W)[(long long)(k0 + kk) * (DD / 4) + n4];
            *(float4*)&ws[kk][n4 * 4] = v;
        }
        __syncthreads();

        #pragma unroll
        for (int k = 0; k < 32; k++) {
            float4 wv = *(const float4*)&ws[k][tx * 4];
            #pragma unroll
            for (int m = 0; m < 4; m++) {
                float xv = xs[ty * 4 + m][k];
                acc[m].x += xv * wv.x;
                acc[m].y += xv * wv.y;
                acc[m].z += xv * wv.z;
                acc[m].w += xv * wv.w;
            }
        }
        __syncthreads();
    }

    // store h as fp16 (half2 pairs; 8 B per thread-row)
    #pragma unroll
    for (int m = 0; m < 4; m++) {
        int row = bm + ty * 4 + m;
        __half2 lo = __floats2half2_rn(acc[m].x, acc[m].y);
        __half2 hi = __floats2half2_rn(acc[m].z, acc[m].w);
        uint2 pack;
        pack.x = *(uint32_t*)&lo;
        pack.y = *(uint32_t*)&hi;
        ((uint2*)g_hh)[row * 32 + tx] = pack;
    }

    // s1 / s2 (each warp owns full 128-col rows) -> direct stores (fp32 accs)
    const int c = tx * 4;
    float4 a1 = *(const float4*)&a[c];
    float4 a2 = *(const float4*)&a[DD + c];
    #pragma unroll
    for (int m = 0; m < 4; m++) {
        float p1 = acc[m].x * a1.x + acc[m].y * a1.y + acc[m].z * a1.z + acc[m].w * a1.w;
        float p2 = acc[m].x * a2.x + acc[m].y * a2.y + acc[m].z * a2.z + acc[m].w * a2.w;
        #pragma unroll
        for (int o = 16; o > 0; o >>= 1) {
            p1 += __shfl_xor_sync(0xffffffffu, p1, o);
            p2 += __shfl_xor_sync(0xffffffffu, p2, o);
        }
        if (tx == 0) {
            int row = bm + ty * 4 + m;
            g_s1[row] = p1;
            g_s2[row] = p2;
        }
    }

    // partial column sums over this block's 64 rows (fp32 accs)
    if (threadIdx.x < 128) shc[threadIdx.x] = 0.0f;
    __syncthreads();
    float4 cs = make_float4(0.f, 0.f, 0.f, 0.f);
    #pragma unroll
    for (int m = 0; m < 4; m++) {
        cs.x += acc[m].x; cs.y += acc[m].y; cs.z += acc[m].z; cs.w += acc[m].w;
    }
    atomicAdd(&shc[c], cs.x);
    atomicAdd(&shc[c + 1], cs.y);
    atomicAdd(&shc[c + 2], cs.z);
    atomicAdd(&shc[c + 3], cs.w);
    __syncthreads();
    if (threadIdx.x < 128) g_ShPart[blockIdx.x][threadIdx.x] = shc[threadIdx.x];

    // last-gemm-block-done reduces ShPart -> Sh (fence+counter, deterministic)
    __threadfence();
    if (threadIdx.x == 0)
        s_flag = (atomicAdd(&g_done, 1) == NBLK_GEMM - 1);
    __syncthreads();
    if (s_flag) {
        __threadfence();                        // acquire: see all ShPart writes
        const int col  = threadIdx.x & 127;
        const int part = threadIdx.x >> 7;      // 0..3, each sums 64 blocks
        float s = 0.0f;
        #pragma unroll 8
        for (int b = part * 64; b < part * 64 + 64; b++) s += g_ShPart[b][col];
        red[part][col] = s;
        __syncthreads();
        if (threadIdx.x < 128)
            g_Sh[threadIdx.x] = red[0][threadIdx.x] + red[1][threadIdx.x]
                              + red[2][threadIdx.x] + red[3][threadIdx.x];
        if (threadIdx.x == 0) g_done = 0;       // self-clean for next replay
    }
}

// ---------------- out: warp per row; bitmap dedup; fp16 gather (8 B/lane,
//   half the L2 traffic); 4-way unroll. Re-zeroes g_cnt[row] for next replay.
__global__ void k_out(float* __restrict__ out) {
    __shared__ int      sc[8][ROWCAP];          // 6 KB
    __shared__ float    sw[8][ROWCAP];          // 6 KB
    __shared__ unsigned bmp[8][NN / 32];        // 16 KB: per-warp 16384-bit bitmap

    const int warp = threadIdx.x >> 5;
    const int lane = threadIdx.x & 31;
    const int row = blockIdx.x * 8 + warp;

    {
        uint4* bv = (uint4*)bmp[warp];
        uint4 z = make_uint4(0u, 0u, 0u, 0u);
        #pragma unroll
        for (int i = 0; i < 4; i++) bv[lane + i * 32] = z;
    }

    int cnt = g_cnt[row];
    if (cnt > ROWCAP) cnt = ROWCAP;
    const int base = row * ROWCAP;
    const float s1i = g_s1[row];

    for (int j = lane; j < cnt; j += 32) sc[warp][j] = g_cols[base + j];
    __syncwarp();

    if (lane == 0) g_cnt[row] = 0;

    for (int j = lane; j < cnt; j += 32) {
        int c = sc[warp][j];
        unsigned bit = 1u << (c & 31);
        unsigned old = atomicOr(&bmp[warp][c >> 5], bit);
        float w = 0.0f;
        if (!(old & bit)) {
            float e = s1i + __ldg(&g_s2[c]);
            e = (e > 0.0f) ? e : 0.2f * e;       // LeakyReLU(0.2)
            w = __expf(e) - 1.0f;                // exp(e) - exp(0)
        }
        sw[warp][j] = w;
    }
    __syncwarp();

    const uint2* hb = (const uint2*)g_hh;        // 4 halfs per lane per row
    float4 acc = make_float4(0.f, 0.f, 0.f, 0.f);
    float wsum = 0.0f;

    int t = 0;
    for (; t + 4 <= cnt; t += 4) {
        const int   c0 = sc[warp][t],     c1 = sc[warp][t + 1];
        const int   c2 = sc[warp][t + 2], c3 = sc[warp][t + 3];
        const float w0 = sw[warp][t],     w1 = sw[warp][t + 1];
        const float w2 = sw[warp][t + 2], w3 = sw[warp][t + 3];
        const uint2 p0 = hb[c0 * 32 + lane];
        const uint2 p1 = hb[c1 * 32 + lane];
        const uint2 p2 = hb[c2 * 32 + lane];
        const uint2 p3 = hb[c3 * 32 + lane];
        float2 l0 = __half22float2(*(const __half2*)&p0.x), h0 = __half22float2(*(const __half2*)&p0.y);
        float2 l1 = __half22float2(*(const __half2*)&p1.x), h1 = __half22float2(*(const __half2*)&p1.y);
        float2 l2 = __half22float2(*(const __half2*)&p2.x), h2 = __half22float2(*(const __half2*)&p2.y);
        float2 l3 = __half22float2(*(const __half2*)&p3.x), h3 = __half22float2(*(const __half2*)&p3.y);
        acc.x += w0 * l0.x; acc.y += w0 * l0.y; acc.z += w0 * h0.x; acc.w += w0 * h0.y; wsum += w0;
        acc.x += w1 * l1.x; acc.y += w1 * l1.y; acc.z += w1 * h1.x; acc.w += w1 * h1.y; wsum += w1;
        acc.x += w2 * l2.x; acc.y += w2 * l2.y; acc.z += w2 * h2.x; acc.w += w2 * h2.y; wsum += w2;
        acc.x += w3 * l3.x; acc.y += w3 * l3.y; acc.z += w3 * h3.x; acc.w += w3 * h3.y; wsum += w3;
    }
    for (; t < cnt; t++) {
        const int   c0 = sc[warp][t];
        const float w0 = sw[warp][t];
        const uint2 p0 = hb[c0 * 32 + lane];
        float2 l0 = __half22float2(*(const __half2*)&p0.x), h0 = __half22float2(*(const __half2*)&p0.y);
        acc.x += w0 * l0.x; acc.y += w0 * l0.y; acc.z += w0 * h0.x; acc.w += w0 * h0.y;
        wsum += w0;
    }

    const float4 sh = ((const float4*)g_Sh)[lane];
    const float inv = 1.0f / ((float)NN + wsum);
    float4 o;
    o.x = (sh.x + acc.x) * inv;
    o.y = (sh.y + acc.y) * inv;
    o.z = (sh.z + acc.z) * inv;
    o.w = (sh.w + acc.w) * inv;
    ((float4*)out)[row * 32 + lane] = o;
}

// ---------------- launcher: 2 graph nodes ----------------
extern "C" void kernel_launch(void* const* d_in, const int* in_sizes, int n_in,
                              void* d_out, int out_size) {
    const float* x  = (const float*)d_in[0];   // [16384,128] f32
    const void*  ei = d_in[1];                 // [2,524288] int64 (or int32 — detected)
    const float* W  = (const float*)d_in[2];   // [128,128] f32
    const float* a  = (const float*)d_in[3];   // [256] f32
    float* out = (float*)d_out;                // [16384,128] f32

    k_main<<<NBLK_GEMM + NBLK_FILL, 512>>>(x, W, a, ei);
    k_out<<<NN / 8, 256>>>(out);
}

// round 12
// speedup vs baseline: 1.7317x; 1.0072x over previous
#include <cuda_runtime.h>
#include <cuda_bf16.h>
#include <cuda_fp16.h>
#include <cstdint>

// Problem constants (fixed by the dataset problem)
#define NN   16384          // nodes
#define DD   128            // feature dim (in == out)
#define EE   524288         // edges
#define ROWCAP 192          // per-row slot cap (max expected degree ~57)
#define NBLK_GEMM (NN / 64) // 256
#define FILL_U 4
#define FILL_THREADS 512
#define FILL_EBLK (FILL_THREADS * FILL_U)          // 2048 edges/block
#define NBLK_FILL (EE / FILL_EBLK)                 // 256

// ---------------- device scratch (no allocations allowed) ----------------
__device__ __half g_hh[NN * DD];               // 4 MB   h = x @ W, fp16 (gather-only use)
__device__ float g_s1[NN];
__device__ float g_s2[NN];
__device__ float g_Sh[DD];                     // total column sums (fp32, from accumulators)
__device__ float g_ShPart[NBLK_GEMM][DD];      // per-gemm-block partial column sums
__device__ int   g_done;                       // gemm-block completion counter (self-reset)
__device__ int   g_cnt[NN];                    // zero at start of every call (self-cleaning)
__device__ int   g_cols[NN * ROWCAP];          // slotted adjacency, 12.6 MB

// ---------------- fused kernel: blocks [0,256) gemm, blocks [256,512) edge fill
//   (byte-identical to the 49.4us R11 measurement)
__global__ void k_main(const float* __restrict__ x, const float* __restrict__ W,
                       const float* __restrict__ a, const void* __restrict__ ei) {
    __shared__ float xs[64][36];    // [m][k], padded          (gemm branch)
    __shared__ float ws[32][128];   // [k][n]                  (gemm branch)
    __shared__ float shc[128];      // block column sums       (gemm branch)
    __shared__ float red[4][128];   // ShPart reduction        (last gemm block)
    __shared__ int   s_flag;        // is64 (fill) / last-block (gemm)

    if (blockIdx.x >= NBLK_GEMM) {
        // ---------------- fill branch ----------------
        if (threadIdx.x == 0) {
            const int* p = (const int*)ei;
            int z = 0;
            #pragma unroll
            for (int i = 0; i < 16; i++) z += (p[2 * i + 1] == 0);
            s_flag = (z == 16);      // int64-LE, values<2^31 -> odd words zero
        }
        __syncthreads();
        const bool is64 = (s_flag != 0);

        const int base = (blockIdx.x - NBLK_GEMM) * FILL_EBLK + threadIdx.x;
        int rr[FILL_U], cc[FILL_U];
        if (is64) {
            const long long* p = (const long long*)ei;
            #pragma unroll
            for (int u = 0; u < FILL_U; u++) {
                int e = base + u * FILL_THREADS;
                rr[u] = (int)p[e];
                cc[u] = (int)p[(long long)EE + e];
            }
        } else {
            const int* p = (const int*)ei;
            #pragma unroll
            for (int u = 0; u < FILL_U; u++) {
                int e = base + u * FILL_THREADS;
                rr[u] = p[e];
                cc[u] = p[EE + e];
            }
        }
        #pragma unroll
        for (int u = 0; u < FILL_U; u++) {
            int slot = atomicAdd(&g_cnt[rr[u]], 1);
            if (slot < ROWCAP) g_cols[rr[u] * ROWCAP + slot] = cc[u];
        }
        return;
    }

    // ---------------- gemm branch ----------------
    const int tx = threadIdx.x & 31;        // 0..31 -> cols tx*4 .. tx*4+3
    const int ty = threadIdx.x >> 5;        // 0..15 -> rows ty*4 .. ty*4+3
    const int bm = blockIdx.x * 64;

    float4 acc[4];
    #pragma unroll
    for (int m = 0; m < 4; m++) acc[m] = make_float4(0.f, 0.f, 0.f, 0.f);

    for (int k0 = 0; k0 < DD; k0 += 32) {
        {   // x tile: 64 rows x 32 k = 512 float4, one per thread
            int i = threadIdx.x;
            int r = i >> 3, c4 = i & 7;
            float4 v = ((const float4*)x)[(long long)(bm + r) * (DD / 4) + (k0 >> 2) + c4];
            *(float4*)&xs[r][c4 * 4] = v;
        }
        #pragma unroll
        for (int i = 0; i < 2; i++) {   // W tile: 32 k x 128 n = 1024 float4
            int idx = threadIdx.x + i * 512;
            int kk = idx >> 5, n4 = idx & 31;
            float4 v = ((const float4*)W)[(long long)(k0 + kk) * (DD / 4) + n4];
            *(float4*)&ws[kk][n4 * 4] = v;
        }
        __syncthreads();

        #pragma unroll
        for (int k = 0; k < 32; k++) {
            float4 wv = *(const float4*)&ws[k][tx * 4];
            #pragma unroll
            for (int m = 0; m < 4; m++) {
                float xv = xs[ty * 4 + m][k];
                acc[m].x += xv * wv.x;
                acc[m].y += xv * wv.y;
                acc[m].z += xv * wv.z;
                acc[m].w += xv * wv.w;
            }
        }
        __syncthreads();
    }

    // store h as fp16 (half2 pairs; 8 B per thread-row)
    #pragma unroll
    for (int m = 0; m < 4; m++) {
        int row = bm + ty * 4 + m;
        __half2 lo = __floats2half2_rn(acc[m].x, acc[m].y);
        __half2 hi = __floats2half2_rn(acc[m].z, acc[m].w);
        uint2 pack;
        pack.x = *(uint32_t*)&lo;
        pack.y = *(uint32_t*)&hi;
        ((uint2*)g_hh)[row * 32 + tx] = pack;
    }

    // s1 / s2 (each warp owns full 128-col rows) -> direct stores (fp32 accs)
    const int c = tx * 4;
    float4 a1 = *(const float4*)&a[c];
    float4 a2 = *(const float4*)&a[DD + c];
    #pragma unroll
    for (int m = 0; m < 4; m++) {
        float p1 = acc[m].x * a1.x + acc[m].y * a1.y + acc[m].z * a1.z + acc[m].w * a1.w;
        float p2 = acc[m].x * a2.x + acc[m].y * a2.y + acc[m].z * a2.z + acc[m].w * a2.w;
        #pragma unroll
        for (int o = 16; o > 0; o >>= 1) {
            p1 += __shfl_xor_sync(0xffffffffu, p1, o);
            p2 += __shfl_xor_sync(0xffffffffu, p2, o);
        }
        if (tx == 0) {
            int row = bm + ty * 4 + m;
            g_s1[row] = p1;
            g_s2[row] = p2;
        }
    }

    // partial column sums over this block's 64 rows (fp32 accs)
    if (threadIdx.x < 128) shc[threadIdx.x] = 0.0f;
    __syncthreads();
    float4 cs = make_float4(0.f, 0.f, 0.f, 0.f);
    #pragma unroll
    for (int m = 0; m < 4; m++) {
        cs.x += acc[m].x; cs.y += acc[m].y; cs.z += acc[m].z; cs.w += acc[m].w;
    }
    atomicAdd(&shc[c], cs.x);
    atomicAdd(&shc[c + 1], cs.y);
    atomicAdd(&shc[c + 2], cs.z);
    atomicAdd(&shc[c + 3], cs.w);
    __syncthreads();
    if (threadIdx.x < 128) g_ShPart[blockIdx.x][threadIdx.x] = shc[threadIdx.x];

    // last-gemm-block-done reduces ShPart -> Sh (fence+counter, deterministic)
    __threadfence();
    if (threadIdx.x == 0)
        s_flag = (atomicAdd(&g_done, 1) == NBLK_GEMM - 1);
    __syncthreads();
    if (s_flag) {
        __threadfence();                        // acquire: see all ShPart writes
        const int col  = threadIdx.x & 127;
        const int part = threadIdx.x >> 7;      // 0..3, each sums 64 blocks
        float s = 0.0f;
        #pragma unroll 8
        for (int b = part * 64; b < part * 64 + 64; b++) s += g_ShPart[b][col];
        red[part][col] = s;
        __syncthreads();
        if (threadIdx.x < 128)
            g_Sh[threadIdx.x] = red[0][threadIdx.x] + red[1][threadIdx.x]
                              + red[2][threadIdx.x] + red[3][threadIdx.x];
        if (threadIdx.x == 0) g_done = 0;       // self-clean for next replay
    }
}

// ---------------- out: warp per row; bitmap dedup; fused (c,w) int2 smem
//   (1 LDS.64/neighbor); wsum hoisted to the weight pass (shfl-reduce);
//   8-way unrolled fp16 gather. Re-zeroes g_cnt[row] for next replay.
__global__ void k_out(float* __restrict__ out) {
    __shared__ int2     scw[8][ROWCAP];         // 12 KB: .x = col, .y = w bits
    __shared__ unsigned bmp[8][NN / 32];        // 16 KB: per-warp 16384-bit bitmap

    const int warp = threadIdx.x >> 5;
    const int lane = threadIdx.x & 31;
    const int row = blockIdx.x * 8 + warp;

    {
        uint4* bv = (uint4*)bmp[warp];
        uint4 z = make_uint4(0u, 0u, 0u, 0u);
        #pragma unroll
        for (int i = 0; i < 4; i++) bv[lane + i * 32] = z;
    }

    int cnt = g_cnt[row];
    if (cnt > ROWCAP) cnt = ROWCAP;
    const int base = row * ROWCAP;
    const float s1i = g_s1[row];

    for (int j = lane; j < cnt; j += 32) scw[warp][j].x = g_cols[base + j];
    __syncwarp();

    if (lane == 0) g_cnt[row] = 0;

    // weight pass: dedup via bitmap, store w beside c, accumulate wsum once
    float wsum = 0.0f;
    for (int j = lane; j < cnt; j += 32) {
        int c = scw[warp][j].x;
        unsigned bit = 1u << (c & 31);
        unsigned old = atomicOr(&bmp[warp][c >> 5], bit);
        float w = 0.0f;
        if (!(old & bit)) {
            float e = s1i + __ldg(&g_s2[c]);
            e = (e > 0.0f) ? e : 0.2f * e;       // LeakyReLU(0.2)
            w = __expf(e) - 1.0f;                // exp(e) - exp(0)
        }
        scw[warp][j].y = __float_as_int(w);
        wsum += w;
    }
    #pragma unroll
    for (int o = 16; o > 0; o >>= 1)
        wsum += __shfl_xor_sync(0xffffffffu, wsum, o);
    __syncwarp();

    const uint2* hb = (const uint2*)g_hh;        // 4 halfs per lane per row
    float4 acc = make_float4(0.f, 0.f, 0.f, 0.f);

    int t = 0;
    for (; t + 8 <= cnt; t += 8) {
        int2 e0 = scw[warp][t],     e1 = scw[warp][t + 1];
        int2 e2 = scw[warp][t + 2], e3 = scw[warp][t + 3];
        int2 e4 = scw[warp][t + 4], e5 = scw[warp][t + 5];
        int2 e6 = scw[warp][t + 6], e7 = scw[warp][t + 7];
        const uint2 p0 = hb[e0.x * 32 + lane];
        const uint2 p1 = hb[e1.x * 32 + lane];
        const uint2 p2 = hb[e2.x * 32 + lane];
        const uint2 p3 = hb[e3.x * 32 + lane];
        const uint2 p4 = hb[e4.x * 32 + lane];
        const uint2 p5 = hb[e5.x * 32 + lane];
        const uint2 p6 = hb[e6.x * 32 + lane];
        const uint2 p7 = hb[e7.x * 32 + lane];
        #define ACCUM(p, e) do {                                               \
            float2 _l = __half22float2(*(const __half2*)&(p).x);               \
            float2 _h = __half22float2(*(const __half2*)&(p).y);               \
            float _w = __int_as_float((e).y);                                  \
            acc.x += _w * _l.x; acc.y += _w * _l.y;                            \
            acc.z += _w * _h.x; acc.w += _w * _h.y;                            \
        } while (0)
        ACCUM(p0, e0); ACCUM(p1, e1); ACCUM(p2, e2); ACCUM(p3, e3);
        ACCUM(p4, e4); ACCUM(p5, e5); ACCUM(p6, e6); ACCUM(p7, e7);
    }
    for (; t < cnt; t++) {
        int2 e0 = scw[warp][t];
        const uint2 p0 = hb[e0.x * 32 + lane];
        ACCUM(p0, e0);
    }
    #undef ACCUM

    const float4 sh = ((const float4*)g_Sh)[lane];
    const float inv = 1.0f / ((float)NN + wsum);
    float4 o;
    o.x = (sh.x + acc.x) * inv;
    o.y = (sh.y + acc.y) * inv;
    o.z = (sh.z + acc.z) * inv;
    o.w = (sh.w + acc.w) * inv;
    ((float4*)out)[row * 32 + lane] = o;
}

// ---------------- launcher: 2 graph nodes ----------------
extern "C" void kernel_launch(void* const* d_in, const int* in_sizes, int n_in,
                              void* d_out, int out_size) {
    const float* x  = (const float*)d_in[0];   // [16384,128] f32
    const void*  ei = d_in[1];                 // [2,524288] int64 (or int32 — detected)
    const float* W  = (const float*)d_in[2];   // [128,128] f32
    const float* a  = (const float*)d_in[3];   // [256] f32
    float* out = (float*)d_out;                // [16384,128] f32

    k_main<<<NBLK_GEMM + NBLK_FILL, 512>>>(x, W, a, ei);
    k_out<<<NN / 8, 256>>>(out);
}